// round 1
// baseline (speedup 1.0000x reference)
#include <cuda_runtime.h>
#include <math.h>

#define Bq 8192
#define Fq 26
#define Dq 32
#define Vq 100000
#define Hq 128
#define NPAIR 351      // 26*27/2 symmetric pairs
#define KMLP 832       // F*D
#define Uq 400

// ---------------- scratch (no cudaMalloc allowed) ----------------
__device__ float g_wsym[NPAIR * Hq];             // symmetrized W_cin0 (pair-major)
__device__ int   g_pi[NPAIR];
__device__ int   g_pj[NPAIR];
__device__ float g_embed[Bq * Fq * Dq];          // gathered embeddings (B, 26, 32)
__device__ float g_lin[Bq];
__device__ float g_x1[(size_t)Bq * Dq * Hq];     // x1 stored (B, d, h)
__device__ float g_cin1[Bq * Hq];
__device__ float g_S[(size_t)Bq * Fq * Hq];      // S (B, i, j) = sum_d X0*x1
__device__ float g_cin2[Bq * Hq];
__device__ float g_h1[Bq * Uq];
__device__ float g_h2[Bq * Uq];

typedef unsigned long long ull;

__device__ __forceinline__ void fma2(ull &acc, ull c, ull w) {
    asm("fma.rn.f32x2 %0, %1, %2, %0;" : "+l"(acc) : "l"(c), "l"(w));
}
__device__ __forceinline__ ull pack2(float x, float y) {
    ull r; asm("mov.b64 %0, {%1, %2};" : "=l"(r) : "f"(x), "f"(y)); return r;
}
__device__ __forceinline__ float2 unpack2(ull v) {
    float2 f; asm("mov.b64 {%0, %1}, %2;" : "=f"(f.x), "=f"(f.y) : "l"(v)); return f;
}

// ---------------- prep: symmetrize W_cin0 over (i,j) pairs ----------------
__global__ void prep_kernel(const float* __restrict__ W0) {
    int t = blockIdx.x * blockDim.x + threadIdx.x;
    if (t >= NPAIR * Hq) return;
    int p = t >> 7, h = t & 127;
    int i = 0, rem = p;
    while (rem >= Fq - i) { rem -= Fq - i; i++; }
    int j = i + rem;
    float w = W0[(i * Fq + j) * Hq + h];
    if (i != j) w += W0[(j * Fq + i) * Hq + h];
    g_wsym[t] = w;
    if (h == 0) { g_pi[p] = i; g_pj[p] = j; }
}

// ---------------- gather embeddings ----------------
__global__ void gather_kernel(const int* __restrict__ idx, const float* __restrict__ E) {
    int e = blockIdx.x * blockDim.x + threadIdx.x;
    if (e >= Bq * Fq * Dq) return;
    int d = e & 31;
    int r = e >> 5;
    int i = r % Fq;
    int b = r / Fq;
    int v = __ldg(&idx[b * Fq + i]);
    g_embed[e] = __ldg(&E[((size_t)i * Vq + v) * Dq + d]);
}

// ---------------- linear term ----------------
__global__ void lin_kernel(const int* __restrict__ idx, const float* __restrict__ w_lin,
                           const float* __restrict__ b_lin) {
    int b = blockIdx.x * blockDim.x + threadIdx.x;
    if (b >= Bq) return;
    float a = b_lin[0];
#pragma unroll
    for (int f = 0; f < Fq; f++) a += (float)idx[b * Fq + f] * w_lin[f];
    g_lin[b] = a;
}

// ---------------- x1[b,h,d] = sum_{i<=j} c_ij(d) * wsym[ij,h] ----------------
// one block per batch row, thread = h. f32x2 packed FMA over d pairs.
__global__ __launch_bounds__(128) void x1_kernel() {
    int b = blockIdx.x;
    int h = threadIdx.x;
    __shared__ float sx[Fq * Dq];
    __shared__ ulonglong2 sc[NPAIR * 8];   // c[p][d] as f32x2 pairs: 44928 B
    const float* eb = g_embed + (size_t)b * Fq * Dq;
    for (int e = h; e < Fq * Dq; e += 128) sx[e] = eb[e];
    __syncthreads();
    float* scf = (float*)sc;
    for (int e = h; e < NPAIR * Dq; e += 128) {
        int p = e >> 5, d = e & 31;
        scf[e] = sx[g_pi[p] * Dq + d] * sx[g_pj[p] * Dq + d];
    }
    __syncthreads();

    ull acc[16];
#pragma unroll
    for (int v = 0; v < 16; v++) acc[v] = 0ULL;

    const float* wp = g_wsym + h;
    for (int p = 0; p < NPAIR; p++) {
        float w = __ldg(&wp[p * Hq]);           // coalesced over h
        ull w2 = pack2(w, w);
#pragma unroll
        for (int v = 0; v < 8; v++) {
            ulonglong2 cc = sc[p * 8 + v];      // broadcast LDS.128
            fma2(acc[2 * v + 0], cc.x, w2);
            fma2(acc[2 * v + 1], cc.y, w2);
        }
    }

    float cin1 = 0.f;
    float* xout = g_x1 + (size_t)b * Dq * Hq + h;
#pragma unroll
    for (int v = 0; v < 16; v++) {
        float2 f = unpack2(acc[v]);
        int d = 2 * v;
        xout[(size_t)d * Hq] = f.x;             // coalesced (fixed d, h contiguous)
        xout[(size_t)(d + 1) * Hq] = f.y;
        cin1 += f.x + f.y;
    }
    g_cin1[b * Hq + h] = cin1;
}

// ---------------- S[b,i,j] = sum_d embed[b,i,d] * x1[b,d,j] ----------------
__global__ __launch_bounds__(128) void S_kernel() {
    int b = blockIdx.x, j = threadIdx.x;
    __shared__ float sx[Fq * Dq];
    const float* eb = g_embed + (size_t)b * Fq * Dq;
    for (int e = j; e < Fq * Dq; e += 128) sx[e] = eb[e];
    __syncthreads();
    float acc[Fq];
#pragma unroll
    for (int i = 0; i < Fq; i++) acc[i] = 0.f;
    const float* xp = g_x1 + (size_t)b * Dq * Hq + j;
#pragma unroll 4
    for (int d = 0; d < Dq; d++) {
        float xv = xp[(size_t)d * Hq];
#pragma unroll
        for (int i = 0; i < Fq; i++) acc[i] += sx[i * Dq + d] * xv;
    }
    float* sp = g_S + (size_t)b * Fq * Hq + j;
#pragma unroll
    for (int i = 0; i < Fq; i++) sp[(size_t)i * Hq] = acc[i];
}

// ---------------- generic fp32 GEMM, f32x2 inner, bias+relu epilogue ----------------
// C[M,N] = A[M,K] @ B[K,N]; BM=128, BN=64, BK=16; 256 thr; 4x8 per thread.
__global__ __launch_bounds__(256) void gemm_kernel(
    const float* __restrict__ A, const float* __restrict__ Bm,
    const float* __restrict__ bias, float* __restrict__ C,
    int M, int N, int K, int relu)
{
    __shared__ float As[16][132];
    __shared__ float Bs[16][64];
    int tid = threadIdx.x;
    int m0 = blockIdx.y * 128, n0 = blockIdx.x * 64;
    int ty = tid >> 3;          // 0..31 -> rows ty*4
    int tx = tid & 7;           // 0..7  -> cols tx*8
    ull acc[4][4];
#pragma unroll
    for (int r = 0; r < 4; r++)
#pragma unroll
        for (int c = 0; c < 4; c++) acc[r][c] = 0ULL;

    for (int k0 = 0; k0 < K; k0 += 16) {
#pragma unroll
        for (int it = 0; it < 2; it++) {
            int idx = tid + it * 256;
            int m = idx >> 2, kq = idx & 3;
            float4 v = *(const float4*)(A + (size_t)(m0 + m) * K + k0 + kq * 4);
            As[kq * 4 + 0][m] = v.x; As[kq * 4 + 1][m] = v.y;
            As[kq * 4 + 2][m] = v.z; As[kq * 4 + 3][m] = v.w;
        }
        {
            int k = tid >> 4, nq = tid & 15;
            int col = n0 + nq * 4;
            float4 v = make_float4(0.f, 0.f, 0.f, 0.f);
            if (col + 3 < N)   // N % 4 == 0 for all uses
                v = *(const float4*)(Bm + (size_t)(k0 + k) * N + col);
            *(float4*)&Bs[k][nq * 4] = v;
        }
        __syncthreads();
#pragma unroll
        for (int k = 0; k < 16; k++) {
            float4 a = *(const float4*)&As[k][ty * 4];
            ulonglong2 u0 = *(const ulonglong2*)&Bs[k][tx * 8];
            ulonglong2 u1 = *(const ulonglong2*)&Bs[k][tx * 8 + 4];
            ull a0 = pack2(a.x, a.x), a1 = pack2(a.y, a.y);
            ull a2 = pack2(a.z, a.z), a3 = pack2(a.w, a.w);
            fma2(acc[0][0], u0.x, a0); fma2(acc[0][1], u0.y, a0); fma2(acc[0][2], u1.x, a0); fma2(acc[0][3], u1.y, a0);
            fma2(acc[1][0], u0.x, a1); fma2(acc[1][1], u0.y, a1); fma2(acc[1][2], u1.x, a1); fma2(acc[1][3], u1.y, a1);
            fma2(acc[2][0], u0.x, a2); fma2(acc[2][1], u0.y, a2); fma2(acc[2][2], u1.x, a2); fma2(acc[2][3], u1.y, a2);
            fma2(acc[3][0], u0.x, a3); fma2(acc[3][1], u0.y, a3); fma2(acc[3][2], u1.x, a3); fma2(acc[3][3], u1.y, a3);
        }
        __syncthreads();
    }
#pragma unroll
    for (int r = 0; r < 4; r++) {
        int row = m0 + ty * 4 + r;   // M % 128 == 0, always in range
#pragma unroll
        for (int c = 0; c < 4; c++) {
            float2 f = unpack2(acc[r][c]);
            int col = n0 + tx * 8 + c * 2;
            if (col < N) {
                float v = f.x + (bias ? bias[col] : 0.f);
                if (relu) v = fmaxf(v, 0.f);
                C[(size_t)row * N + col] = v;
            }
            if (col + 1 < N) {
                float v = f.y + (bias ? bias[col + 1] : 0.f);
                if (relu) v = fmaxf(v, 0.f);
                C[(size_t)row * N + col + 1] = v;
            }
        }
    }
}

// ---------------- final head: sigmoid(total @ w_out + b_out) ----------------
__global__ void final_kernel(const float* __restrict__ dense,
                             const float* __restrict__ w_out,
                             const float* __restrict__ b_out,
                             float* __restrict__ out) {
    int gt = blockIdx.x * blockDim.x + threadIdx.x;
    int b = gt >> 5, lane = gt & 31;
    if (b >= Bq) return;
    float a = 0.f;
    const float* c1 = g_cin1 + b * Hq;
    const float* c2 = g_cin2 + b * Hq;
    const float* hh = g_h2 + b * Uq;
    for (int t = lane; t < Hq; t += 32) a += c1[t] * w_out[1 + t];
    for (int t = lane; t < Hq; t += 32) a += c2[t] * w_out[1 + Hq + t];
    for (int t = lane; t < Uq; t += 32) a += hh[t] * w_out[1 + 2 * Hq + t];
    if (lane < 13) a += dense[b * 13 + lane] * w_out[1 + 2 * Hq + Uq + lane];
#pragma unroll
    for (int o = 16; o > 0; o >>= 1) a += __shfl_down_sync(0xffffffffu, a, o);
    if (lane == 0) {
        float tot = a + g_lin[b] * w_out[0] + b_out[0];
        float o;
        if (tot >= 0.f) { o = 1.f / (1.f + expf(-tot)); }
        else            { float e = expf(tot); o = e / (1.f + e); }
        out[b] = o;
    }
}

extern "C" void kernel_launch(void* const* d_in, const int* in_sizes, int n_in,
                              void* d_out, int out_size) {
    (void)in_sizes; (void)n_in; (void)out_size;
    const float* dense  = (const float*)d_in[0];
    const int*   sparse = (const int*)  d_in[1];
    const float* E      = (const float*)d_in[2];
    const float* W0     = (const float*)d_in[3];
    const float* Wc1    = (const float*)d_in[4];
    const float* W1     = (const float*)d_in[5];
    const float* b1     = (const float*)d_in[6];
    const float* W2     = (const float*)d_in[7];
    const float* b2     = (const float*)d_in[8];
    const float* w_lin  = (const float*)d_in[9];
    const float* b_lin  = (const float*)d_in[10];
    const float* w_out  = (const float*)d_in[11];
    const float* b_out  = (const float*)d_in[12];
    float* out = (float*)d_out;

    void *pS, *pE, *pH1, *pH2, *pC2;
    cudaGetSymbolAddress(&pS,  g_S);
    cudaGetSymbolAddress(&pE,  g_embed);
    cudaGetSymbolAddress(&pH1, g_h1);
    cudaGetSymbolAddress(&pH2, g_h2);
    cudaGetSymbolAddress(&pC2, g_cin2);

    prep_kernel<<<(NPAIR * Hq + 255) / 256, 256>>>(W0);
    gather_kernel<<<(Bq * Fq * Dq + 255) / 256, 256>>>(sparse, E);
    lin_kernel<<<(Bq + 255) / 256, 256>>>(sparse, w_lin, b_lin);
    x1_kernel<<<Bq, 128>>>();
    S_kernel<<<Bq, 128>>>();
    // cin2 = S (8192 x 3328) @ W_cin1 (3328 x 128)
    gemm_kernel<<<dim3((Hq + 63) / 64, Bq / 128), 256>>>(
        (const float*)pS, Wc1, nullptr, (float*)pC2, Bq, Hq, Fq * Hq, 0);
    // h1 = relu(embed (8192 x 832) @ W1 + b1)
    gemm_kernel<<<dim3((Uq + 63) / 64, Bq / 128), 256>>>(
        (const float*)pE, W1, b1, (float*)pH1, Bq, Uq, KMLP, 1);
    // h2 = relu(h1 @ W2 + b2)
    gemm_kernel<<<dim3((Uq + 63) / 64, Bq / 128), 256>>>(
        (const float*)pH1, W2, b2, (float*)pH2, Bq, Uq, Uq, 1);
    final_kernel<<<(Bq * 32 + 255) / 256, 256>>>(dense, w_out, b_out, out);
}

// round 2
// speedup vs baseline: 1.2406x; 1.2406x over previous
#include <cuda_runtime.h>
#include <math.h>

#define Bq 8192
#define Fq 26
#define Dq 32
#define Vq 100000
#define Hq 128
#define NPAIR 351      // 26*27/2 symmetric pairs
#define PTILE 117      // 351 = 3 * 117
#define KMLP 832       // F*D
#define Uq 400

// ---------------- scratch (no cudaMalloc allowed) ----------------
__device__ float g_wsym[NPAIR * Hq];             // symmetrized W_cin0 (pair-major)
__device__ int   g_pi[NPAIR];
__device__ int   g_pj[NPAIR];
__device__ float g_embed[Bq * Fq * Dq];          // gathered embeddings (B, 26, 32)
__device__ float g_lin[Bq];
__device__ float g_cin1[Bq * Hq];
__device__ float g_S[(size_t)Bq * Fq * Hq];      // S (B, i, h) = sum_d X0 * x1
__device__ float g_cin2[Bq * Hq];
__device__ float g_h1[Bq * Uq];
__device__ float g_h2[Bq * Uq];

typedef unsigned long long ull;

__device__ __forceinline__ void fma2(ull &acc, ull c, ull w) {
    asm("fma.rn.f32x2 %0, %1, %2, %0;" : "+l"(acc) : "l"(c), "l"(w));
}
__device__ __forceinline__ ull pack2(float x, float y) {
    ull r; asm("mov.b64 %0, {%1, %2};" : "=l"(r) : "f"(x), "f"(y)); return r;
}
__device__ __forceinline__ float2 unpack2(ull v) {
    float2 f; asm("mov.b64 {%0, %1}, %2;" : "=f"(f.x), "=f"(f.y) : "l"(v)); return f;
}

// ---------------- prep: symmetrize W_cin0 over (i,j) pairs ----------------
__global__ void prep_kernel(const float* __restrict__ W0) {
    int t = blockIdx.x * blockDim.x + threadIdx.x;
    if (t >= NPAIR * Hq) return;
    int p = t >> 7, h = t & 127;
    int i = 0, rem = p;
    while (rem >= Fq - i) { rem -= Fq - i; i++; }
    int j = i + rem;
    float w = W0[(i * Fq + j) * Hq + h];
    if (i != j) w += W0[(j * Fq + i) * Hq + h];
    g_wsym[t] = w;
    if (h == 0) { g_pi[p] = i; g_pj[p] = j; }
}

// ---------------- gather embeddings (float4 vectorized) ----------------
__global__ void gather_kernel(const int* __restrict__ idx, const float* __restrict__ E) {
    int e = blockIdx.x * blockDim.x + threadIdx.x;       // float4 index
    if (e >= Bq * Fq * (Dq / 4)) return;
    int q = e & 7;              // which float4 in the 32-float row
    int r = e >> 3;
    int i = r % Fq;
    int b = r / Fq;
    int v = __ldg(&idx[b * Fq + i]);
    float4 val = __ldg((const float4*)(E + ((size_t)i * Vq + v) * Dq) + q);
    ((float4*)g_embed)[e] = val;
}

// ---------------- linear term ----------------
__global__ void lin_kernel(const int* __restrict__ idx, const float* __restrict__ w_lin,
                           const float* __restrict__ b_lin) {
    int b = blockIdx.x * blockDim.x + threadIdx.x;
    if (b >= Bq) return;
    float a = b_lin[0];
#pragma unroll
    for (int f = 0; f < Fq; f++) a += (float)idx[b * Fq + f] * w_lin[f];
    g_lin[b] = a;
}

// ---------------- fused x1 + cin1 + S ----------------
// block = one batch row, 64 threads. Thread t computes h-columns t and t+64 of
// x1[b,:,h] in registers (32 d-values each, packed f32x2), then cin1 and
// S[b,i,h] = sum_d embed[b,i,d] * x1[b,d,h] directly from registers.
__global__ __launch_bounds__(64) void x1s_kernel() {
    int b = blockIdx.x;
    int tid = threadIdx.x;                    // 0..63
    __shared__ float sx[Fq * Dq];             // 3328 B
    __shared__ ulonglong2 sc[PTILE * 8];      // 14976 B: c[p][d] as f32x2 pairs
    const float* eb = g_embed + (size_t)b * Fq * Dq;
    for (int e = tid; e < Fq * Dq; e += 64) sx[e] = eb[e];

    ull acc0[16], acc1[16];
#pragma unroll
    for (int v = 0; v < 16; v++) { acc0[v] = 0ULL; acc1[v] = 0ULL; }

    float* scf = (float*)sc;
#pragma unroll 1
    for (int t = 0; t < 3; t++) {
        __syncthreads();    // t=0: sx ready; t>0: previous tile fully consumed
        int pbase = t * PTILE;
        for (int e = tid; e < PTILE * Dq; e += 64) {
            int p = e >> 5, d = e & 31;
            scf[e] = sx[g_pi[pbase + p] * Dq + d] * sx[g_pj[pbase + p] * Dq + d];
        }
        __syncthreads();
        const float* wp = g_wsym + (size_t)pbase * Hq;
#pragma unroll 3
        for (int p = 0; p < PTILE; p++) {
            float w0 = __ldg(&wp[p * Hq + tid]);
            float w1 = __ldg(&wp[p * Hq + tid + 64]);
            ull w20 = pack2(w0, w0), w21 = pack2(w1, w1);
#pragma unroll
            for (int v = 0; v < 8; v++) {
                ulonglong2 cc = sc[p * 8 + v];       // broadcast LDS.128
                fma2(acc0[2 * v + 0], cc.x, w20);
                fma2(acc0[2 * v + 1], cc.y, w20);
                fma2(acc1[2 * v + 0], cc.x, w21);
                fma2(acc1[2 * v + 1], cc.y, w21);
            }
        }
    }

    // unpack x1 columns to plain floats
    float x0f[Dq], x1f[Dq];
    float c0 = 0.f, c1 = 0.f;
#pragma unroll
    for (int v = 0; v < 16; v++) {
        float2 f0 = unpack2(acc0[v]);
        float2 f1 = unpack2(acc1[v]);
        x0f[2 * v] = f0.x; x0f[2 * v + 1] = f0.y;
        x1f[2 * v] = f1.x; x1f[2 * v + 1] = f1.y;
        c0 += f0.x + f0.y;
        c1 += f1.x + f1.y;
    }
    g_cin1[b * Hq + tid] = c0;
    g_cin1[b * Hq + tid + 64] = c1;

    // S[b,i,h] = sum_d sx[i,d] * x1[d,h]  (x1 columns live in registers)
    float* sp = g_S + (size_t)b * Fq * Hq;
#pragma unroll 2
    for (int i = 0; i < Fq; i++) {
        float s0 = 0.f, s1 = 0.f;
#pragma unroll
        for (int d = 0; d < Dq; d++) {
            float e = sx[i * Dq + d];
            s0 += e * x0f[d];
            s1 += e * x1f[d];
        }
        sp[i * Hq + tid] = s0;
        sp[i * Hq + tid + 64] = s1;
    }
}

// ---------------- generic fp32 GEMM, f32x2 inner, bias+relu epilogue ----------------
// C[M,N] = A[M,K] @ B[K,N]; BM=128, BN=64, BK=16; 256 thr; 4x8 per thread.
__global__ __launch_bounds__(256) void gemm_kernel(
    const float* __restrict__ A, const float* __restrict__ Bm,
    const float* __restrict__ bias, float* __restrict__ C,
    int M, int N, int K, int relu)
{
    __shared__ float As[16][132];
    __shared__ float Bs[16][64];
    int tid = threadIdx.x;
    int m0 = blockIdx.y * 128, n0 = blockIdx.x * 64;
    int ty = tid >> 3;          // 0..31 -> rows ty*4
    int tx = tid & 7;           // 0..7  -> cols tx*8
    ull acc[4][4];
#pragma unroll
    for (int r = 0; r < 4; r++)
#pragma unroll
        for (int c = 0; c < 4; c++) acc[r][c] = 0ULL;

    for (int k0 = 0; k0 < K; k0 += 16) {
#pragma unroll
        for (int it = 0; it < 2; it++) {
            int idx = tid + it * 256;
            int m = idx >> 2, kq = idx & 3;
            float4 v = *(const float4*)(A + (size_t)(m0 + m) * K + k0 + kq * 4);
            As[kq * 4 + 0][m] = v.x; As[kq * 4 + 1][m] = v.y;
            As[kq * 4 + 2][m] = v.z; As[kq * 4 + 3][m] = v.w;
        }
        {
            int k = tid >> 4, nq = tid & 15;
            int col = n0 + nq * 4;
            float4 v = make_float4(0.f, 0.f, 0.f, 0.f);
            if (col + 3 < N)   // N % 4 == 0 for all uses
                v = *(const float4*)(Bm + (size_t)(k0 + k) * N + col);
            *(float4*)&Bs[k][nq * 4] = v;
        }
        __syncthreads();
#pragma unroll
        for (int k = 0; k < 16; k++) {
            float4 a = *(const float4*)&As[k][ty * 4];
            ulonglong2 u0 = *(const ulonglong2*)&Bs[k][tx * 8];
            ulonglong2 u1 = *(const ulonglong2*)&Bs[k][tx * 8 + 4];
            ull a0 = pack2(a.x, a.x), a1 = pack2(a.y, a.y);
            ull a2 = pack2(a.z, a.z), a3 = pack2(a.w, a.w);
            fma2(acc[0][0], u0.x, a0); fma2(acc[0][1], u0.y, a0); fma2(acc[0][2], u1.x, a0); fma2(acc[0][3], u1.y, a0);
            fma2(acc[1][0], u0.x, a1); fma2(acc[1][1], u0.y, a1); fma2(acc[1][2], u1.x, a1); fma2(acc[1][3], u1.y, a1);
            fma2(acc[2][0], u0.x, a2); fma2(acc[2][1], u0.y, a2); fma2(acc[2][2], u1.x, a2); fma2(acc[2][3], u1.y, a2);
            fma2(acc[3][0], u0.x, a3); fma2(acc[3][1], u0.y, a3); fma2(acc[3][2], u1.x, a3); fma2(acc[3][3], u1.y, a3);
        }
        __syncthreads();
    }
#pragma unroll
    for (int r = 0; r < 4; r++) {
        int row = m0 + ty * 4 + r;   // M % 128 == 0, always in range
#pragma unroll
        for (int c = 0; c < 4; c++) {
            float2 f = unpack2(acc[r][c]);
            int col = n0 + tx * 8 + c * 2;
            if (col < N) {
                float v = f.x + (bias ? bias[col] : 0.f);
                if (relu) v = fmaxf(v, 0.f);
                C[(size_t)row * N + col] = v;
            }
            if (col + 1 < N) {
                float v = f.y + (bias ? bias[col + 1] : 0.f);
                if (relu) v = fmaxf(v, 0.f);
                C[(size_t)row * N + col + 1] = v;
            }
        }
    }
}

// ---------------- final head: sigmoid(total @ w_out + b_out) ----------------
__global__ void final_kernel(const float* __restrict__ dense,
                             const float* __restrict__ w_out,
                             const float* __restrict__ b_out,
                             float* __restrict__ out) {
    int gt = blockIdx.x * blockDim.x + threadIdx.x;
    int b = gt >> 5, lane = gt & 31;
    if (b >= Bq) return;
    float a = 0.f;
    const float* c1 = g_cin1 + b * Hq;
    const float* c2 = g_cin2 + b * Hq;
    const float* hh = g_h2 + b * Uq;
    for (int t = lane; t < Hq; t += 32) a += c1[t] * w_out[1 + t];
    for (int t = lane; t < Hq; t += 32) a += c2[t] * w_out[1 + Hq + t];
    for (int t = lane; t < Uq; t += 32) a += hh[t] * w_out[1 + 2 * Hq + t];
    if (lane < 13) a += dense[b * 13 + lane] * w_out[1 + 2 * Hq + Uq + lane];
#pragma unroll
    for (int o = 16; o > 0; o >>= 1) a += __shfl_down_sync(0xffffffffu, a, o);
    if (lane == 0) {
        float tot = a + g_lin[b] * w_out[0] + b_out[0];
        float o;
        if (tot >= 0.f) { o = 1.f / (1.f + expf(-tot)); }
        else            { float e = expf(tot); o = e / (1.f + e); }
        out[b] = o;
    }
}

extern "C" void kernel_launch(void* const* d_in, const int* in_sizes, int n_in,
                              void* d_out, int out_size) {
    (void)in_sizes; (void)n_in; (void)out_size;
    const float* dense  = (const float*)d_in[0];
    const int*   sparse = (const int*)  d_in[1];
    const float* E      = (const float*)d_in[2];
    const float* W0     = (const float*)d_in[3];
    const float* Wc1    = (const float*)d_in[4];
    const float* W1     = (const float*)d_in[5];
    const float* b1     = (const float*)d_in[6];
    const float* W2     = (const float*)d_in[7];
    const float* b2     = (const float*)d_in[8];
    const float* w_lin  = (const float*)d_in[9];
    const float* b_lin  = (const float*)d_in[10];
    const float* w_out  = (const float*)d_in[11];
    const float* b_out  = (const float*)d_in[12];
    float* out = (float*)d_out;

    void *pS, *pE, *pH1, *pH2, *pC2;
    cudaGetSymbolAddress(&pS,  g_S);
    cudaGetSymbolAddress(&pE,  g_embed);
    cudaGetSymbolAddress(&pH1, g_h1);
    cudaGetSymbolAddress(&pH2, g_h2);
    cudaGetSymbolAddress(&pC2, g_cin2);

    prep_kernel<<<(NPAIR * Hq + 255) / 256, 256>>>(W0);
    gather_kernel<<<(Bq * Fq * (Dq / 4) + 255) / 256, 256>>>(sparse, E);
    lin_kernel<<<(Bq + 255) / 256, 256>>>(sparse, w_lin, b_lin);
    x1s_kernel<<<Bq, 64>>>();
    // cin2 = S (8192 x 3328) @ W_cin1 (3328 x 128)
    gemm_kernel<<<dim3((Hq + 63) / 64, Bq / 128), 256>>>(
        (const float*)pS, Wc1, nullptr, (float*)pC2, Bq, Hq, Fq * Hq, 0);
    // h1 = relu(embed (8192 x 832) @ W1 + b1)
    gemm_kernel<<<dim3((Uq + 63) / 64, Bq / 128), 256>>>(
        (const float*)pE, W1, b1, (float*)pH1, Bq, Uq, KMLP, 1);
    // h2 = relu(h1 @ W2 + b2)
    gemm_kernel<<<dim3((Uq + 63) / 64, Bq / 128), 256>>>(
        (const float*)pH1, W2, b2, (float*)pH2, Bq, Uq, Uq, 1);
    final_kernel<<<(Bq * 32 + 255) / 256, 256>>>(dense, w_out, b_out, out);
}

// round 3
// speedup vs baseline: 1.6570x; 1.3357x over previous
#include <cuda_runtime.h>
#include <cuda_bf16.h>
#include <math.h>

#define Bq 8192
#define Fq 26
#define Dq 32
#define Vq 100000
#define Hq 128
#define NPAIR 351      // 26*27/2 symmetric pairs
#define KPAD 352       // padded pair count (mma K)
#define NKP  176       // KPAD/2 packed k-pairs
#define KMLP 832       // F*D
#define Uq 400

// ---------------- scratch (no cudaMalloc allowed) ----------------
__device__ float    g_wsym[NPAIR * Hq];          // symmetrized W_cin0 (pair-major)
__device__ int      g_pij[KPAD];                 // pi | pj<<8 (padded)
__device__ unsigned g_whi[NKP * Hq];             // wsym bf16-hi packed (2 k per u32)
__device__ unsigned g_wlo[NKP * Hq];             // wsym bf16-lo packed
__device__ float    g_embed[Bq * Fq * Dq];       // gathered embeddings (B, 26, 32)
__device__ float    g_lin[Bq];
__device__ float    g_x1[(size_t)Bq * Dq * Hq];  // x1 (b,d,h) = GEMM M x N
__device__ float    g_cin1[Bq * Hq];
__device__ float    g_S[(size_t)Bq * Fq * Hq];   // S (b, i, h)
__device__ float    g_cin2[Bq * Hq];
__device__ float    g_h1[Bq * Uq];
__device__ float    g_h2[Bq * Uq];

// ---------------- helpers ----------------
// split two fp32 into packed bf16 hi and lo words (lo = exact residual rounded)
__device__ __forceinline__ void split2(float x, float y, unsigned &hi, unsigned &lo) {
    unsigned xh = (unsigned)__bfloat16_as_ushort(__float2bfloat16_rn(x));
    unsigned yh = (unsigned)__bfloat16_as_ushort(__float2bfloat16_rn(y));
    float xr = x - __uint_as_float(xh << 16);   // bf16->fp32 is exact via bit shift
    float yr = y - __uint_as_float(yh << 16);
    unsigned xl = (unsigned)__bfloat16_as_ushort(__float2bfloat16_rn(xr));
    unsigned yl = (unsigned)__bfloat16_as_ushort(__float2bfloat16_rn(yr));
    hi = xh | (yh << 16);
    lo = xl | (yl << 16);
}

__device__ __forceinline__ void mma16816(float c[4], const unsigned a[4],
                                         unsigned b0, unsigned b1) {
    asm volatile(
        "mma.sync.aligned.m16n8k16.row.col.f32.bf16.bf16.f32 "
        "{%0,%1,%2,%3}, {%4,%5,%6,%7}, {%8,%9}, {%0,%1,%2,%3};"
        : "+f"(c[0]), "+f"(c[1]), "+f"(c[2]), "+f"(c[3])
        : "r"(a[0]), "r"(a[1]), "r"(a[2]), "r"(a[3]), "r"(b0), "r"(b1));
}

// ---------------- prep1: symmetrize W_cin0 over (i,j) pairs ----------------
__global__ void prep_kernel(const float* __restrict__ W0) {
    int t = blockIdx.x * blockDim.x + threadIdx.x;
    if (t == 0) g_pij[NPAIR] = 0;                 // pad pair
    if (t >= NPAIR * Hq) return;
    int p = t >> 7, h = t & 127;
    int i = 0, rem = p;
    while (rem >= Fq - i) { rem -= Fq - i; i++; }
    int j = i + rem;
    float w = W0[(i * Fq + j) * Hq + h];
    if (i != j) w += W0[(j * Fq + i) * Hq + h];
    g_wsym[t] = w;
    if (h == 0) g_pij[p] = i | (j << 8);
}

// ---------------- prep2: bf16-split + k-pair-pack wsym ----------------
__global__ void prep2_kernel() {
    int t = blockIdx.x * blockDim.x + threadIdx.x;
    if (t >= NKP * Hq) return;
    int kp = t >> 7, h = t & 127;
    int p0 = 2 * kp, p1 = 2 * kp + 1;
    float w0 = (p0 < NPAIR) ? g_wsym[p0 * Hq + h] : 0.f;
    float w1 = (p1 < NPAIR) ? g_wsym[p1 * Hq + h] : 0.f;
    unsigned hi, lo;
    split2(w0, w1, hi, lo);
    g_whi[t] = hi;
    g_wlo[t] = lo;
}

// ---------------- gather embeddings (float4 vectorized) ----------------
__global__ void gather_kernel(const int* __restrict__ idx, const float* __restrict__ E) {
    int e = blockIdx.x * blockDim.x + threadIdx.x;       // float4 index
    if (e >= Bq * Fq * (Dq / 4)) return;
    int q = e & 7;
    int r = e >> 3;
    int i = r % Fq;
    int b = r / Fq;
    int v = __ldg(&idx[b * Fq + i]);
    float4 val = __ldg((const float4*)(E + ((size_t)i * Vq + v) * Dq) + q);
    ((float4*)g_embed)[e] = val;
}

// ---------------- linear term ----------------
__global__ void lin_kernel(const int* __restrict__ idx, const float* __restrict__ w_lin,
                           const float* __restrict__ b_lin) {
    int b = blockIdx.x * blockDim.x + threadIdx.x;
    if (b >= Bq) return;
    float a = b_lin[0];
#pragma unroll
    for (int f = 0; f < Fq; f++) a += (float)idx[b * Fq + f] * w_lin[f];
    g_lin[b] = a;
}

// ---------------- x1 GEMM: x1[(b,d),h] = P[(b,d),p] @ wsym[p,h] ----------------
// block = 4 batch rows -> M-tile 128 (m = bl*32+d), N = 128, K = 352 in 22 tiles of 16.
// A (P) built on the fly from embeddings; bf16 2-term split; 8 warps (wm 0..3, wn 0..1).
__global__ __launch_bounds__(256) void x1_mma_kernel() {
    __shared__ float    sx[4 * Fq * Dq];        // 13312 B
    __shared__ int      spij[KPAD];             // 1408 B
    __shared__ unsigned Ahi[128][12], Alo[128][12];   // 8 kpairs + pad -> 12288 B
    __shared__ unsigned Bhi[8][136],  Blo[8][136];    // 8704 B

    int tid  = threadIdx.x;
    int warp = tid >> 5, lane = tid & 31;
    int gid  = lane >> 2, tg = lane & 3;
    int wm   = warp & 3, wn = warp >> 2;        // wm: 32 rows, wn: 64 cols

    const float* eb = g_embed + (size_t)blockIdx.x * 4 * Fq * Dq;
    for (int e = tid; e < 4 * Fq * Dq; e += 256) sx[e] = eb[e];
    for (int e = tid; e < KPAD; e += 256) spij[e] = g_pij[e];

    float c[2][8][4];
#pragma unroll
    for (int mt = 0; mt < 2; mt++)
#pragma unroll
        for (int nt = 0; nt < 8; nt++)
#pragma unroll
            for (int r = 0; r < 4; r++) c[mt][nt][r] = 0.f;

    __syncthreads();

#pragma unroll 1
    for (int t = 0; t < 22; t++) {
        // build A tile: 128 m x 8 kpairs
#pragma unroll
        for (int it = 0; it < 4; it++) {
            int idx = it * 256 + tid;
            int kp = idx >> 7, m = idx & 127;
            int bl = m >> 5, d = m & 31;
            int k0 = t * 16 + kp * 2;
            int pij0 = spij[k0], pij1 = spij[k0 + 1];
            const float* sb = sx + bl * (Fq * Dq) + d;
            float a0 = sb[(pij0 & 255) * Dq] * sb[(pij0 >> 8) * Dq];
            float a1 = sb[(pij1 & 255) * Dq] * sb[(pij1 >> 8) * Dq];
            split2(a0, a1, Ahi[m][kp], Alo[m][kp]);
        }
        // load B tile: 8 kpairs x 128 n from prepacked wsym
#pragma unroll
        for (int it = 0; it < 4; it++) {
            int idx = it * 256 + tid;
            int kp = idx >> 7, n = idx & 127;
            int g = (t * 8 + kp) * Hq + n;
            Bhi[kp][n] = g_whi[g];
            Blo[kp][n] = g_wlo[g];
        }
        __syncthreads();

        unsigned ah[2][4], al[2][4];
#pragma unroll
        for (int mt = 0; mt < 2; mt++) {
            int mb = wm * 32 + mt * 16;
            ah[mt][0] = Ahi[mb + gid][tg];     al[mt][0] = Alo[mb + gid][tg];
            ah[mt][1] = Ahi[mb + gid + 8][tg]; al[mt][1] = Alo[mb + gid + 8][tg];
            ah[mt][2] = Ahi[mb + gid][tg + 4]; al[mt][2] = Alo[mb + gid][tg + 4];
            ah[mt][3] = Ahi[mb + gid + 8][tg + 4]; al[mt][3] = Alo[mb + gid + 8][tg + 4];
        }
#pragma unroll
        for (int nt = 0; nt < 8; nt++) {
            int nb = wn * 64 + nt * 8;
            unsigned bh0 = Bhi[tg][nb + gid], bh1 = Bhi[tg + 4][nb + gid];
            unsigned bl0 = Blo[tg][nb + gid], bl1 = Blo[tg + 4][nb + gid];
#pragma unroll
            for (int mt = 0; mt < 2; mt++) {
                mma16816(c[mt][nt], ah[mt], bh0, bh1);
                mma16816(c[mt][nt], ah[mt], bl0, bl1);
                mma16816(c[mt][nt], al[mt], bh0, bh1);
            }
        }
        __syncthreads();
    }

    // epilogue: write x1 (M x N row-major)
    size_t rowbase = (size_t)blockIdx.x * 128;
#pragma unroll
    for (int mt = 0; mt < 2; mt++) {
        int r0 = wm * 32 + mt * 16 + gid;
#pragma unroll
        for (int nt = 0; nt < 8; nt++) {
            int col = wn * 64 + nt * 8 + 2 * tg;
            *(float2*)&g_x1[(rowbase + r0) * Hq + col]     = make_float2(c[mt][nt][0], c[mt][nt][1]);
            *(float2*)&g_x1[(rowbase + r0 + 8) * Hq + col] = make_float2(c[mt][nt][2], c[mt][nt][3]);
        }
    }
}

// ---------------- S + cin1: S[b,i,h] = sum_d e[b,i,d] * x1[b,d,h] ----------------
__global__ __launch_bounds__(128) void s_kernel() {
    int b = blockIdx.x, h = threadIdx.x;
    __shared__ float sx[Fq * Dq];
    const float* eb = g_embed + (size_t)b * Fq * Dq;
    for (int e = h; e < Fq * Dq; e += 128) sx[e] = eb[e];
    __syncthreads();
    float acc[Fq];
#pragma unroll
    for (int i = 0; i < Fq; i++) acc[i] = 0.f;
    float c1 = 0.f;
    const float* xp = g_x1 + (size_t)b * Dq * Hq + h;
#pragma unroll 4
    for (int d = 0; d < Dq; d++) {
        float xv = xp[(size_t)d * Hq];
        c1 += xv;
#pragma unroll
        for (int i = 0; i < Fq; i++) acc[i] += sx[i * Dq + d] * xv;
    }
    g_cin1[b * Hq + h] = c1;
    float* sp = g_S + (size_t)b * Fq * Hq + h;
#pragma unroll
    for (int i = 0; i < Fq; i++) sp[(size_t)i * Hq] = acc[i];
}

// ---------------- generic GEMM via bf16-split mma ----------------
// C[M,N] = A[M,K] @ B[K,N] (+bias, relu). BM=64, BN=128, BK=16; 256 thr, 8 warps
// (wm 0..1 -> 32 rows, wn 0..3 -> 32 cols). K must be a multiple of 16; M of 64.
__global__ __launch_bounds__(256) void gemm_mma(
    const float* __restrict__ A, const float* __restrict__ Bm,
    const float* __restrict__ bias, float* __restrict__ C,
    int M, int N, int K, int relu)
{
    __shared__ unsigned Ahi[64][12], Alo[64][12];   // 8 kpairs + pad
    __shared__ unsigned Bhi[8][136], Blo[8][136];

    int tid  = threadIdx.x;
    int warp = tid >> 5, lane = tid & 31;
    int gid  = lane >> 2, tg = lane & 3;
    int wm   = warp & 1, wn = warp >> 1;
    int m0 = blockIdx.y * 64, n0 = blockIdx.x * 128;

    float c[2][4][4];
#pragma unroll
    for (int mt = 0; mt < 2; mt++)
#pragma unroll
        for (int nt = 0; nt < 4; nt++)
#pragma unroll
            for (int r = 0; r < 4; r++) c[mt][nt][r] = 0.f;

#pragma unroll 1
    for (int k0 = 0; k0 < K; k0 += 16) {
        {   // A tile: 64 rows x 16 k = 256 float4, one per thread
            int m = tid >> 2, q = tid & 3;
            float4 v = *(const float4*)(A + (size_t)(m0 + m) * K + k0 + q * 4);
            split2(v.x, v.y, Ahi[m][2 * q],     Alo[m][2 * q]);
            split2(v.z, v.w, Ahi[m][2 * q + 1], Alo[m][2 * q + 1]);
        }
#pragma unroll
        for (int it = 0; it < 4; it++) {   // B tile: 8 kpairs x 128 n
            int e = it * 256 + tid;
            int kp = e >> 7, n = e & 127;
            int col = n0 + n;
            float f0 = 0.f, f1 = 0.f;
            if (col < N) {
                f0 = Bm[(size_t)(k0 + 2 * kp) * N + col];
                f1 = Bm[(size_t)(k0 + 2 * kp + 1) * N + col];
            }
            split2(f0, f1, Bhi[kp][n], Blo[kp][n]);
        }
        __syncthreads();

        unsigned ah[2][4], al[2][4];
#pragma unroll
        for (int mt = 0; mt < 2; mt++) {
            int mb = wm * 32 + mt * 16;
            ah[mt][0] = Ahi[mb + gid][tg];         al[mt][0] = Alo[mb + gid][tg];
            ah[mt][1] = Ahi[mb + gid + 8][tg];     al[mt][1] = Alo[mb + gid + 8][tg];
            ah[mt][2] = Ahi[mb + gid][tg + 4];     al[mt][2] = Alo[mb + gid][tg + 4];
            ah[mt][3] = Ahi[mb + gid + 8][tg + 4]; al[mt][3] = Alo[mb + gid + 8][tg + 4];
        }
#pragma unroll
        for (int nt = 0; nt < 4; nt++) {
            int nb = wn * 32 + nt * 8;
            unsigned bh0 = Bhi[tg][nb + gid], bh1 = Bhi[tg + 4][nb + gid];
            unsigned bl0 = Blo[tg][nb + gid], bl1 = Blo[tg + 4][nb + gid];
#pragma unroll
            for (int mt = 0; mt < 2; mt++) {
                mma16816(c[mt][nt], ah[mt], bh0, bh1);
                mma16816(c[mt][nt], ah[mt], bl0, bl1);
                mma16816(c[mt][nt], al[mt], bh0, bh1);
            }
        }
        __syncthreads();
    }

    // epilogue
#pragma unroll
    for (int mt = 0; mt < 2; mt++) {
        int r0 = m0 + wm * 32 + mt * 16 + gid;
#pragma unroll
        for (int nt = 0; nt < 4; nt++) {
            int col = n0 + wn * 32 + nt * 8 + 2 * tg;
            if (col < N) {
                float b0v = bias ? bias[col] : 0.f;
                float b1v = bias ? bias[col + 1] : 0.f;
                float v0 = c[mt][nt][0] + b0v, v1 = c[mt][nt][1] + b1v;
                float v2 = c[mt][nt][2] + b0v, v3 = c[mt][nt][3] + b1v;
                if (relu) {
                    v0 = fmaxf(v0, 0.f); v1 = fmaxf(v1, 0.f);
                    v2 = fmaxf(v2, 0.f); v3 = fmaxf(v3, 0.f);
                }
                *(float2*)&C[(size_t)r0 * N + col]       = make_float2(v0, v1);
                *(float2*)&C[(size_t)(r0 + 8) * N + col] = make_float2(v2, v3);
            }
        }
    }
}

// ---------------- final head: sigmoid(total @ w_out + b_out) ----------------
__global__ void final_kernel(const float* __restrict__ dense,
                             const float* __restrict__ w_out,
                             const float* __restrict__ b_out,
                             float* __restrict__ out) {
    int gt = blockIdx.x * blockDim.x + threadIdx.x;
    int b = gt >> 5, lane = gt & 31;
    if (b >= Bq) return;
    float a = 0.f;
    const float* c1 = g_cin1 + b * Hq;
    const float* c2 = g_cin2 + b * Hq;
    const float* hh = g_h2 + b * Uq;
    for (int t = lane; t < Hq; t += 32) a += c1[t] * w_out[1 + t];
    for (int t = lane; t < Hq; t += 32) a += c2[t] * w_out[1 + Hq + t];
    for (int t = lane; t < Uq; t += 32) a += hh[t] * w_out[1 + 2 * Hq + t];
    if (lane < 13) a += dense[b * 13 + lane] * w_out[1 + 2 * Hq + Uq + lane];
#pragma unroll
    for (int o = 16; o > 0; o >>= 1) a += __shfl_down_sync(0xffffffffu, a, o);
    if (lane == 0) {
        float tot = a + g_lin[b] * w_out[0] + b_out[0];
        float o;
        if (tot >= 0.f) { o = 1.f / (1.f + expf(-tot)); }
        else            { float e = expf(tot); o = e / (1.f + e); }
        out[b] = o;
    }
}

extern "C" void kernel_launch(void* const* d_in, const int* in_sizes, int n_in,
                              void* d_out, int out_size) {
    (void)in_sizes; (void)n_in; (void)out_size;
    const float* dense  = (const float*)d_in[0];
    const int*   sparse = (const int*)  d_in[1];
    const float* E      = (const float*)d_in[2];
    const float* W0     = (const float*)d_in[3];
    const float* Wc1    = (const float*)d_in[4];
    const float* W1     = (const float*)d_in[5];
    const float* b1     = (const float*)d_in[6];
    const float* W2     = (const float*)d_in[7];
    const float* b2     = (const float*)d_in[8];
    const float* w_lin  = (const float*)d_in[9];
    const float* b_lin  = (const float*)d_in[10];
    const float* w_out  = (const float*)d_in[11];
    const float* b_out  = (const float*)d_in[12];
    float* out = (float*)d_out;

    void *pS, *pE, *pH1, *pH2, *pC2;
    cudaGetSymbolAddress(&pS,  g_S);
    cudaGetSymbolAddress(&pE,  g_embed);
    cudaGetSymbolAddress(&pH1, g_h1);
    cudaGetSymbolAddress(&pH2, g_h2);
    cudaGetSymbolAddress(&pC2, g_cin2);

    prep_kernel<<<(NPAIR * Hq + 255) / 256, 256>>>(W0);
    prep2_kernel<<<(NKP * Hq + 255) / 256, 256>>>();
    gather_kernel<<<(Bq * Fq * (Dq / 4) + 255) / 256, 256>>>(sparse, E);
    lin_kernel<<<(Bq + 255) / 256, 256>>>(sparse, w_lin, b_lin);
    x1_mma_kernel<<<Bq / 4, 256>>>();
    s_kernel<<<Bq, 128>>>();
    // cin2 = S (8192 x 3328) @ Wc1 (3328 x 128)
    gemm_mma<<<dim3(1, Bq / 64), 256>>>(
        (const float*)pS, Wc1, nullptr, (float*)pC2, Bq, Hq, Fq * Hq, 0);
    // h1 = relu(embed (8192 x 832) @ W1 + b1)
    gemm_mma<<<dim3((Uq + 127) / 128, Bq / 64), 256>>>(
        (const float*)pE, W1, b1, (float*)pH1, Bq, Uq, KMLP, 1);
    // h2 = relu(h1 @ W2 + b2)
    gemm_mma<<<dim3((Uq + 127) / 128, Bq / 64), 256>>>(
        (const float*)pH1, W2, b2, (float*)pH2, Bq, Uq, Uq, 1);
    final_kernel<<<(Bq * 32 + 255) / 256, 256>>>(dense, w_out, b_out, out);
}

// round 4
// speedup vs baseline: 2.1514x; 1.2983x over previous
#include <cuda_runtime.h>
#include <cuda_bf16.h>
#include <math.h>

#define Bq 8192
#define Fq 26
#define Dq 32
#define Vq 100000
#define Hq 128
#define NPAIR 351      // 26*27/2 symmetric pairs
#define KPAD 352       // padded pair count (x1 mma K)
#define NKP  176       // KPAD/2 packed k-pairs
#define Uq 400
#define KP_CIN2 1664   // 3328/2
#define KP_MLP1 416    // 832/2
#define KP_MLP2 200    // 400/2

// ---------------- scratch (no cudaMalloc allowed) ----------------
__device__ float    g_wsym[NPAIR * Hq];
__device__ int      g_pij[KPAD];
__device__ __align__(16) unsigned g_whi[NKP * Hq];
__device__ __align__(16) unsigned g_wlo[NKP * Hq];
__device__ __align__(16) float    g_embed[Bq * Fq * Dq];
__device__ __align__(16) unsigned g_Ehi[Bq * KP_MLP1], g_Elo[Bq * KP_MLP1];
__device__ __align__(16) unsigned g_Shi[(size_t)Bq * KP_CIN2], g_Slo[(size_t)Bq * KP_CIN2];
__device__ __align__(16) unsigned g_Wc1hi[KP_CIN2 * Hq], g_Wc1lo[KP_CIN2 * Hq];
__device__ __align__(16) unsigned g_W1hi[KP_MLP1 * Uq], g_W1lo[KP_MLP1 * Uq];
__device__ __align__(16) unsigned g_W2hi[KP_MLP2 * Uq], g_W2lo[KP_MLP2 * Uq];
__device__ __align__(16) unsigned g_H1hi[Bq * KP_MLP2], g_H1lo[Bq * KP_MLP2];
__device__ float    g_lin[Bq];
__device__ float    g_cin1[Bq * Hq];
__device__ float    g_cin2[Bq * Hq];
__device__ float    g_h2[Bq * Uq];

// ---------------- helpers ----------------
__device__ __forceinline__ void split2(float x, float y, unsigned &hi, unsigned &lo) {
    unsigned xh = (unsigned)__bfloat16_as_ushort(__float2bfloat16_rn(x));
    unsigned yh = (unsigned)__bfloat16_as_ushort(__float2bfloat16_rn(y));
    float xr = x - __uint_as_float(xh << 16);
    float yr = y - __uint_as_float(yh << 16);
    unsigned xl = (unsigned)__bfloat16_as_ushort(__float2bfloat16_rn(xr));
    unsigned yl = (unsigned)__bfloat16_as_ushort(__float2bfloat16_rn(yr));
    hi = xh | (yh << 16);
    lo = xl | (yl << 16);
}

__device__ __forceinline__ void mma16816(float c[4], const unsigned a[4],
                                         unsigned b0, unsigned b1) {
    asm volatile(
        "mma.sync.aligned.m16n8k16.row.col.f32.bf16.bf16.f32 "
        "{%0,%1,%2,%3}, {%4,%5,%6,%7}, {%8,%9}, {%0,%1,%2,%3};"
        : "+f"(c[0]), "+f"(c[1]), "+f"(c[2]), "+f"(c[3])
        : "r"(a[0]), "r"(a[1]), "r"(a[2]), "r"(a[3]), "r"(b0), "r"(b1));
}

// ---------------- prep1: symmetrize W_cin0 ----------------
__global__ void prep_kernel(const float* __restrict__ W0) {
    int t = blockIdx.x * blockDim.x + threadIdx.x;
    if (t == 0) g_pij[NPAIR] = 0;
    if (t >= NPAIR * Hq) return;
    int p = t >> 7, h = t & 127;
    int i = 0, rem = p;
    while (rem >= Fq - i) { rem -= Fq - i; i++; }
    int j = i + rem;
    float w = W0[(i * Fq + j) * Hq + h];
    if (i != j) w += W0[(j * Fq + i) * Hq + h];
    g_wsym[t] = w;
    if (h == 0) g_pij[p] = i | (j << 8);
}

// ---------------- prep2: bf16-split + k-pair-pack wsym ----------------
__global__ void prep2_kernel() {
    int t = blockIdx.x * blockDim.x + threadIdx.x;
    if (t >= NKP * Hq) return;
    int kp = t >> 7, h = t & 127;
    int p0 = 2 * kp, p1 = 2 * kp + 1;
    float w0 = (p0 < NPAIR) ? g_wsym[p0 * Hq + h] : 0.f;
    float w1 = (p1 < NPAIR) ? g_wsym[p1 * Hq + h] : 0.f;
    split2(w0, w1, g_whi[t], g_wlo[t]);
}

// ---------------- packB: fp32 [K][N] -> packed [K/2][N] u32 hi/lo ----------------
__global__ void packB_kernel(const float* __restrict__ B, unsigned* __restrict__ hi,
                             unsigned* __restrict__ lo, int Kp, int N) {
    int t = blockIdx.x * blockDim.x + threadIdx.x;
    if (t >= Kp * N) return;
    int kp = t / N, n = t % N;
    split2(B[(size_t)(2 * kp) * N + n], B[(size_t)(2 * kp + 1) * N + n], hi[t], lo[t]);
}

// ---------------- gather: fp32 embed + packed split for MLP1 ----------------
__global__ void gather_kernel(const int* __restrict__ idx, const float* __restrict__ E) {
    int e = blockIdx.x * blockDim.x + threadIdx.x;       // float4 index
    if (e >= Bq * Fq * (Dq / 4)) return;
    int q = e & 7;
    int r = e >> 3;
    int i = r % Fq;
    int b = r / Fq;
    int v = __ldg(&idx[b * Fq + i]);
    float4 val = __ldg((const float4*)(E + ((size_t)i * Vq + v) * Dq) + q);
    ((float4*)g_embed)[e] = val;
    int u = b * KP_MLP1 + (i * 8 + q) * 2;
    split2(val.x, val.y, g_Ehi[u],     g_Elo[u]);
    split2(val.z, val.w, g_Ehi[u + 1], g_Elo[u + 1]);
}

// ---------------- linear term ----------------
__global__ void lin_kernel(const int* __restrict__ idx, const float* __restrict__ w_lin,
                           const float* __restrict__ b_lin) {
    int b = blockIdx.x * blockDim.x + threadIdx.x;
    if (b >= Bq) return;
    float a = b_lin[0];
#pragma unroll
    for (int f = 0; f < Fq; f++) a += (float)idx[b * Fq + f] * w_lin[f];
    g_lin[b] = a;
}

// ---------------- fused x1 GEMM + cin1 + S (packed) ----------------
// block = 4 batch rows; M-tile 128 (m = bl*32+d), N = 128, K = 352 (22 tiles).
// dyn smem: sx | spij | Ahi | Alo | Bhi | Blo | x1s
#define X1_SMEM 102272
__global__ __launch_bounds__(256) void x1s_mma_kernel() {
    extern __shared__ char dynsm[];
    float*    sx   = (float*)(dynsm + 0);          // 3328 f
    int*      spij = (int*)(dynsm + 13312);        // 352
    unsigned* Ahi  = (unsigned*)(dynsm + 14720);   // 128*12
    unsigned* Alo  = (unsigned*)(dynsm + 20864);
    unsigned* Bhi  = (unsigned*)(dynsm + 27008);   // 8*136
    unsigned* Blo  = (unsigned*)(dynsm + 31360);
    float*    x1s  = (float*)(dynsm + 35712);      // 128*130

    int tid  = threadIdx.x;
    int warp = tid >> 5, lane = tid & 31;
    int gid  = lane >> 2, tg = lane & 3;
    int wm   = warp & 3, wn = warp >> 2;

    const float* eb = g_embed + (size_t)blockIdx.x * 4 * Fq * Dq;
    for (int e = tid; e < 4 * Fq * Dq; e += 256) sx[e] = eb[e];
    for (int e = tid; e < KPAD; e += 256) spij[e] = g_pij[e];

    float c[2][8][4];
#pragma unroll
    for (int mt = 0; mt < 2; mt++)
#pragma unroll
        for (int nt = 0; nt < 8; nt++)
#pragma unroll
            for (int r = 0; r < 4; r++) c[mt][nt][r] = 0.f;

    __syncthreads();

#pragma unroll 1
    for (int t = 0; t < 22; t++) {
#pragma unroll
        for (int it = 0; it < 4; it++) {      // build A tile 128 x 8 kp
            int idx = it * 256 + tid;
            int kp = idx >> 7, m = idx & 127;
            int bl = m >> 5, d = m & 31;
            int k0 = t * 16 + kp * 2;
            int pij0 = spij[k0], pij1 = spij[k0 + 1];
            const float* sb = sx + bl * (Fq * Dq) + d;
            float a0 = sb[(pij0 & 255) * Dq] * sb[(pij0 >> 8) * Dq];
            float a1 = sb[(pij1 & 255) * Dq] * sb[(pij1 >> 8) * Dq];
            split2(a0, a1, Ahi[m * 12 + kp], Alo[m * 12 + kp]);
        }
#pragma unroll
        for (int it = 0; it < 4; it++) {      // B tile from prepacked wsym
            int idx = it * 256 + tid;
            int kp = idx >> 7, n = idx & 127;
            int g = (t * 8 + kp) * Hq + n;
            Bhi[kp * 136 + n] = g_whi[g];
            Blo[kp * 136 + n] = g_wlo[g];
        }
        __syncthreads();

        unsigned ah[2][4], al[2][4];
#pragma unroll
        for (int mt = 0; mt < 2; mt++) {
            int mb = wm * 32 + mt * 16;
            ah[mt][0] = Ahi[(mb + gid) * 12 + tg];         al[mt][0] = Alo[(mb + gid) * 12 + tg];
            ah[mt][1] = Ahi[(mb + gid + 8) * 12 + tg];     al[mt][1] = Alo[(mb + gid + 8) * 12 + tg];
            ah[mt][2] = Ahi[(mb + gid) * 12 + tg + 4];     al[mt][2] = Alo[(mb + gid) * 12 + tg + 4];
            ah[mt][3] = Ahi[(mb + gid + 8) * 12 + tg + 4]; al[mt][3] = Alo[(mb + gid + 8) * 12 + tg + 4];
        }
#pragma unroll
        for (int nt = 0; nt < 8; nt++) {
            int nb = wn * 64 + nt * 8;
            unsigned bh0 = Bhi[tg * 136 + nb + gid], bh1 = Bhi[(tg + 4) * 136 + nb + gid];
            unsigned bl0 = Blo[tg * 136 + nb + gid], bl1 = Blo[(tg + 4) * 136 + nb + gid];
#pragma unroll
            for (int mt = 0; mt < 2; mt++) {
                mma16816(c[mt][nt], ah[mt], bh0, bh1);
                mma16816(c[mt][nt], ah[mt], bl0, bl1);
                mma16816(c[mt][nt], al[mt], bh0, bh1);
            }
        }
        __syncthreads();
    }

    // spill x1 tile (128 x 128) to smem
#pragma unroll
    for (int mt = 0; mt < 2; mt++) {
        int r0 = wm * 32 + mt * 16 + gid;
#pragma unroll
        for (int nt = 0; nt < 8; nt++) {
            int col = wn * 64 + nt * 8 + 2 * tg;
            *(float2*)&x1s[r0 * 130 + col]       = make_float2(c[mt][nt][0], c[mt][nt][1]);
            *(float2*)&x1s[(r0 + 8) * 130 + col] = make_float2(c[mt][nt][2], c[mt][nt][3]);
        }
    }
    __syncthreads();

    int bRow0 = blockIdx.x * 4;

    // cin1[b,h] = sum_d x1[b,d,h]  (512 outputs, 2 per thread)
#pragma unroll
    for (int it = 0; it < 2; it++) {
        int o = tid + it * 256;
        int b4 = o >> 7, h = o & 127;
        float a = 0.f;
#pragma unroll
        for (int d = 0; d < Dq; d++) a += x1s[(b4 * 32 + d) * 130 + h];
        g_cin1[(bRow0 + b4) * Hq + h] = a;
    }

    // S[b,i,h] packed: 4*26*64 u32-pairs = 6656, 26 per thread
#pragma unroll 1
    for (int it = 0; it < 26; it++) {
        int o = tid + it * 256;
        int hp = o & 63;
        int rest = o >> 6;
        int i = rest % Fq, b4 = rest / Fq;
        const float* ex = sx + b4 * (Fq * Dq) + i * Dq;
        float s0 = 0.f, s1 = 0.f;
#pragma unroll
        for (int d = 0; d < Dq; d++) {
            float e = ex[d];
            float2 xv = *(const float2*)&x1s[(b4 * 32 + d) * 130 + 2 * hp];
            s0 += e * xv.x;
            s1 += e * xv.y;
        }
        unsigned hi, lo;
        split2(s0, s1, hi, lo);
        size_t u = (size_t)(bRow0 + b4) * KP_CIN2 + i * 64 + hp;
        g_Shi[u] = hi;
        g_Slo[u] = lo;
    }
}

// ---------------- packed GEMM: C[M,N] = A @ B, all operands pre-split ----------------
// BM=128, BN=128, BK=16 (8 kp); 256 thr; 8 warps (wm 0..3 x 32 rows, wn 0..1 x 64 cols).
// double-buffered smem, one sync per k-tile. Kp%8==0, M%128==0, N%4==0 required.
__global__ __launch_bounds__(256) void gemm_pk(
    const unsigned* __restrict__ Agh, const unsigned* __restrict__ Agl, int Kp,
    const unsigned* __restrict__ Bgh, const unsigned* __restrict__ Bgl, int N,
    const float* __restrict__ bias, int relu,
    float* __restrict__ Cf, unsigned* __restrict__ Ch, unsigned* __restrict__ Cl)
{
    __shared__ __align__(16) unsigned sAh[2][128 * 12], sAl[2][128 * 12];
    __shared__ __align__(16) unsigned sBh[2][8 * 132],  sBl[2][8 * 132];

    int tid  = threadIdx.x;
    int warp = tid >> 5, lane = tid & 31;
    int gid  = lane >> 2, tg = lane & 3;
    int wm   = warp & 3, wn = warp >> 2;
    int m0 = blockIdx.y * 128, n0 = blockIdx.x * 128;

    int am = tid >> 1, ahalf = tid & 1;          // A staging: 128 rows x 2 uint4
    int bkp = tid >> 5, bn4 = tid & 31;          // B staging: 8 rows x 32 uint4
    int bcol = n0 + bn4 * 4;

    float c[2][8][4];
#pragma unroll
    for (int mt = 0; mt < 2; mt++)
#pragma unroll
        for (int nt = 0; nt < 8; nt++)
#pragma unroll
            for (int r = 0; r < 4; r++) c[mt][nt][r] = 0.f;

    int T = Kp >> 3;
    // prologue: tile 0
    {
        uint4 xah = *(const uint4*)&Agh[(size_t)(m0 + am) * Kp + ahalf * 4];
        uint4 xal = *(const uint4*)&Agl[(size_t)(m0 + am) * Kp + ahalf * 4];
        uint4 xbh = make_uint4(0, 0, 0, 0), xbl = make_uint4(0, 0, 0, 0);
        if (bcol < N) {
            xbh = *(const uint4*)&Bgh[(size_t)bkp * N + bcol];
            xbl = *(const uint4*)&Bgl[(size_t)bkp * N + bcol];
        }
        *(uint4*)&sAh[0][am * 12 + ahalf * 4] = xah;
        *(uint4*)&sAl[0][am * 12 + ahalf * 4] = xal;
        *(uint4*)&sBh[0][bkp * 132 + bn4 * 4] = xbh;
        *(uint4*)&sBl[0][bkp * 132 + bn4 * 4] = xbl;
    }
    __syncthreads();
    int buf = 0;

#pragma unroll 1
    for (int t = 0; t < T; t++) {
        uint4 xah, xal, xbh, xbl;
        bool have = (t + 1 < T);
        if (have) {
            int k0p = (t + 1) * 8;
            xah = *(const uint4*)&Agh[(size_t)(m0 + am) * Kp + k0p + ahalf * 4];
            xal = *(const uint4*)&Agl[(size_t)(m0 + am) * Kp + k0p + ahalf * 4];
            xbh = make_uint4(0, 0, 0, 0); xbl = make_uint4(0, 0, 0, 0);
            if (bcol < N) {
                xbh = *(const uint4*)&Bgh[(size_t)(k0p + bkp) * N + bcol];
                xbl = *(const uint4*)&Bgl[(size_t)(k0p + bkp) * N + bcol];
            }
        }

        const unsigned* Ah = sAh[buf]; const unsigned* Al = sAl[buf];
        const unsigned* Bh = sBh[buf]; const unsigned* Bl = sBl[buf];
        unsigned ah[2][4], al[2][4];
#pragma unroll
        for (int mt = 0; mt < 2; mt++) {
            int mb = wm * 32 + mt * 16;
            ah[mt][0] = Ah[(mb + gid) * 12 + tg];         al[mt][0] = Al[(mb + gid) * 12 + tg];
            ah[mt][1] = Ah[(mb + gid + 8) * 12 + tg];     al[mt][1] = Al[(mb + gid + 8) * 12 + tg];
            ah[mt][2] = Ah[(mb + gid) * 12 + tg + 4];     al[mt][2] = Al[(mb + gid) * 12 + tg + 4];
            ah[mt][3] = Ah[(mb + gid + 8) * 12 + tg + 4]; al[mt][3] = Al[(mb + gid + 8) * 12 + tg + 4];
        }
#pragma unroll
        for (int nt = 0; nt < 8; nt++) {
            int nb = wn * 64 + nt * 8;
            unsigned bh0 = Bh[tg * 132 + nb + gid], bh1 = Bh[(tg + 4) * 132 + nb + gid];
            unsigned bl0 = Bl[tg * 132 + nb + gid], bl1 = Bl[(tg + 4) * 132 + nb + gid];
#pragma unroll
            for (int mt = 0; mt < 2; mt++) {
                mma16816(c[mt][nt], ah[mt], bh0, bh1);
                mma16816(c[mt][nt], ah[mt], bl0, bl1);
                mma16816(c[mt][nt], al[mt], bh0, bh1);
            }
        }

        if (have) {
            int nb2 = buf ^ 1;
            *(uint4*)&sAh[nb2][am * 12 + ahalf * 4] = xah;
            *(uint4*)&sAl[nb2][am * 12 + ahalf * 4] = xal;
            *(uint4*)&sBh[nb2][bkp * 132 + bn4 * 4] = xbh;
            *(uint4*)&sBl[nb2][bkp * 132 + bn4 * 4] = xbl;
            __syncthreads();
            buf = nb2;
        }
    }

    // epilogue
    int Np = N >> 1;
#pragma unroll
    for (int mt = 0; mt < 2; mt++) {
        int r0 = m0 + wm * 32 + mt * 16 + gid;
#pragma unroll
        for (int nt = 0; nt < 8; nt++) {
            int col = n0 + wn * 64 + nt * 8 + 2 * tg;
            if (col >= N) continue;
            float b0v = bias ? bias[col] : 0.f;
            float b1v = bias ? bias[col + 1] : 0.f;
            float v0 = c[mt][nt][0] + b0v, v1 = c[mt][nt][1] + b1v;
            float v2 = c[mt][nt][2] + b0v, v3 = c[mt][nt][3] + b1v;
            if (relu) {
                v0 = fmaxf(v0, 0.f); v1 = fmaxf(v1, 0.f);
                v2 = fmaxf(v2, 0.f); v3 = fmaxf(v3, 0.f);
            }
            if (Cf) {
                *(float2*)&Cf[(size_t)r0 * N + col]       = make_float2(v0, v1);
                *(float2*)&Cf[(size_t)(r0 + 8) * N + col] = make_float2(v2, v3);
            }
            if (Ch) {
                unsigned hi, lo;
                split2(v0, v1, hi, lo);
                g_H1hi[(size_t)r0 * Np + (col >> 1)] = hi;
                g_H1lo[(size_t)r0 * Np + (col >> 1)] = lo;
                split2(v2, v3, hi, lo);
                g_H1hi[(size_t)(r0 + 8) * Np + (col >> 1)] = hi;
                g_H1lo[(size_t)(r0 + 8) * Np + (col >> 1)] = lo;
            }
        }
    }
    (void)Cl;
}

// ---------------- final head ----------------
__global__ void final_kernel(const float* __restrict__ dense,
                             const float* __restrict__ w_out,
                             const float* __restrict__ b_out,
                             float* __restrict__ out) {
    int gt = blockIdx.x * blockDim.x + threadIdx.x;
    int b = gt >> 5, lane = gt & 31;
    if (b >= Bq) return;
    float a = 0.f;
    const float* c1 = g_cin1 + b * Hq;
    const float* c2 = g_cin2 + b * Hq;
    const float* hh = g_h2 + b * Uq;
    for (int t = lane; t < Hq; t += 32) a += c1[t] * w_out[1 + t];
    for (int t = lane; t < Hq; t += 32) a += c2[t] * w_out[1 + Hq + t];
    for (int t = lane; t < Uq; t += 32) a += hh[t] * w_out[1 + 2 * Hq + t];
    if (lane < 13) a += dense[b * 13 + lane] * w_out[1 + 2 * Hq + Uq + lane];
#pragma unroll
    for (int o = 16; o > 0; o >>= 1) a += __shfl_down_sync(0xffffffffu, a, o);
    if (lane == 0) {
        float tot = a + g_lin[b] * w_out[0] + b_out[0];
        float o;
        if (tot >= 0.f) { o = 1.f / (1.f + expf(-tot)); }
        else            { float e = expf(tot); o = e / (1.f + e); }
        out[b] = o;
    }
}

extern "C" void kernel_launch(void* const* d_in, const int* in_sizes, int n_in,
                              void* d_out, int out_size) {
    (void)in_sizes; (void)n_in; (void)out_size;
    const float* dense  = (const float*)d_in[0];
    const int*   sparse = (const int*)  d_in[1];
    const float* E      = (const float*)d_in[2];
    const float* W0     = (const float*)d_in[3];
    const float* Wc1    = (const float*)d_in[4];
    const float* W1     = (const float*)d_in[5];
    const float* b1     = (const float*)d_in[6];
    const float* W2     = (const float*)d_in[7];
    const float* b2     = (const float*)d_in[8];
    const float* w_lin  = (const float*)d_in[9];
    const float* b_lin  = (const float*)d_in[10];
    const float* w_out  = (const float*)d_in[11];
    const float* b_out  = (const float*)d_in[12];
    float* out = (float*)d_out;

    static int smem_set = 0;
    if (!smem_set) {
        cudaFuncSetAttribute(x1s_mma_kernel,
                             cudaFuncAttributeMaxDynamicSharedMemorySize, X1_SMEM);
        smem_set = 1;
    }

    void *pShi, *pSlo, *pEhi, *pElo, *pWc1hi, *pWc1lo, *pW1hi, *pW1lo,
         *pW2hi, *pW2lo, *pH1hi, *pH1lo, *pC2, *pH2;
    cudaGetSymbolAddress(&pShi, g_Shi);   cudaGetSymbolAddress(&pSlo, g_Slo);
    cudaGetSymbolAddress(&pEhi, g_Ehi);   cudaGetSymbolAddress(&pElo, g_Elo);
    cudaGetSymbolAddress(&pWc1hi, g_Wc1hi); cudaGetSymbolAddress(&pWc1lo, g_Wc1lo);
    cudaGetSymbolAddress(&pW1hi, g_W1hi); cudaGetSymbolAddress(&pW1lo, g_W1lo);
    cudaGetSymbolAddress(&pW2hi, g_W2hi); cudaGetSymbolAddress(&pW2lo, g_W2lo);
    cudaGetSymbolAddress(&pH1hi, g_H1hi); cudaGetSymbolAddress(&pH1lo, g_H1lo);
    cudaGetSymbolAddress(&pC2, g_cin2);   cudaGetSymbolAddress(&pH2, g_h2);

    prep_kernel<<<(NPAIR * Hq + 255) / 256, 256>>>(W0);
    prep2_kernel<<<(NKP * Hq + 255) / 256, 256>>>();
    packB_kernel<<<(KP_CIN2 * Hq + 255) / 256, 256>>>(Wc1, (unsigned*)pWc1hi, (unsigned*)pWc1lo, KP_CIN2, Hq);
    packB_kernel<<<(KP_MLP1 * Uq + 255) / 256, 256>>>(W1, (unsigned*)pW1hi, (unsigned*)pW1lo, KP_MLP1, Uq);
    packB_kernel<<<(KP_MLP2 * Uq + 255) / 256, 256>>>(W2, (unsigned*)pW2hi, (unsigned*)pW2lo, KP_MLP2, Uq);
    gather_kernel<<<(Bq * Fq * (Dq / 4) + 255) / 256, 256>>>(sparse, E);
    lin_kernel<<<(Bq + 255) / 256, 256>>>(sparse, w_lin, b_lin);
    x1s_mma_kernel<<<Bq / 4, 256, X1_SMEM>>>();
    // cin2 = S @ Wc1  (8192 x 3328 x 128)
    gemm_pk<<<dim3(1, Bq / 128), 256>>>(
        (const unsigned*)pShi, (const unsigned*)pSlo, KP_CIN2,
        (const unsigned*)pWc1hi, (const unsigned*)pWc1lo, Hq,
        nullptr, 0, (float*)pC2, nullptr, nullptr);
    // h1 = relu(embed @ W1 + b1) -> packed split only
    gemm_pk<<<dim3((Uq + 127) / 128, Bq / 128), 256>>>(
        (const unsigned*)pEhi, (const unsigned*)pElo, KP_MLP1,
        (const unsigned*)pW1hi, (const unsigned*)pW1lo, Uq,
        b1, 1, nullptr, (unsigned*)pH1hi, (unsigned*)pH1lo);
    // h2 = relu(h1 @ W2 + b2) -> fp32
    gemm_pk<<<dim3((Uq + 127) / 128, Bq / 128), 256>>>(
        (const unsigned*)pH1hi, (const unsigned*)pH1lo, KP_MLP2,
        (const unsigned*)pW2hi, (const unsigned*)pW2lo, Uq,
        b2, 1, (float*)pH2, nullptr, nullptr);
    final_kernel<<<(Bq * 32 + 255) / 256, 256>>>(dense, w_out, b_out, out);
}